// round 9
// baseline (speedup 1.0000x reference)
#include <cuda_runtime.h>

#define NN 100000
#define EE 3200000
#define RR 8
#define NB (NN * RR)
#define SCAN_BLK 1024
#define SCAN_ITEMS 4
#define SCAN_CHUNK (SCAN_BLK * SCAN_ITEMS)              // 4096
#define SCAN_NBLK ((NB + SCAN_CHUNK - 1) / SCAN_CHUNK)  // 196

// ---- device scratch (zero-initialized at load; g_cnt re-zeroed each call in k_scatter) ----
__device__ __align__(16) int  g_cnt[NB];
__device__ __align__(16) int  g_off[NB + 1];
__device__ __align__(16) int  g_bsum[SCAN_NBLK];
__device__ __align__(16) int  g_pos[EE];
__device__ __align__(16) int2 g_srt2[EE];      // {(src<<3)|rel, bits(1/n)} sorted by (dst,rel)
__device__ __align__(16) float g_T[NN * RR * 16];  // T[i][r][:] = x_i @ W_r  (index = packed*16)
__device__ __align__(16) float g_s[NN * 16];       // self term x_i @ root + b
__device__ __align__(16) float g_h[NN * 16];       // layer-1 output

// launch 0: one int atomic per edge -> count + within-bucket position
__global__ void k_hist(const int* __restrict__ dst, const int* __restrict__ et) {
    int e = blockIdx.x * blockDim.x + threadIdx.x;
    if (e >= EE) return;
    int key = dst[e] * RR + et[e];
    g_pos[e] = atomicAdd(&g_cnt[key], 1);
}

// launch 1: per-chunk sums of g_cnt
__global__ void __launch_bounds__(SCAN_BLK) k_scan_reduce() {
    __shared__ int sh[SCAN_BLK];
    int t = threadIdx.x, b = blockIdx.x;
    int i0 = b * SCAN_CHUNK + t * SCAN_ITEMS;
    int s = 0;
#pragma unroll
    for (int j = 0; j < SCAN_ITEMS; j++) {
        int i = i0 + j;
        s += (i < NB) ? g_cnt[i] : 0;
    }
    sh[t] = s;
    __syncthreads();
    for (int ofs = SCAN_BLK / 2; ofs > 0; ofs >>= 1) {
        if (t < ofs) sh[t] += sh[t + ofs];
        __syncthreads();
    }
    if (t == 0) g_bsum[b] = sh[0];
}

// launch 2: full exclusive scan -> g_off (each block redundantly scans the 196 chunk sums)
__global__ void __launch_bounds__(SCAN_BLK) k_scan_write() {
    __shared__ int sbs[256];
    __shared__ int sh[SCAN_BLK];
    int t = threadIdx.x, b = blockIdx.x;

    if (t < 256) sbs[t] = (t < SCAN_NBLK) ? g_bsum[t] : 0;
    __syncthreads();
#pragma unroll
    for (int ofs = 1; ofs < 256; ofs <<= 1) {
        int a = (t >= ofs && t < 256) ? sbs[t - ofs] : 0;
        __syncthreads();
        if (t < 256) sbs[t] += a;
        __syncthreads();
    }
    int boff = (b > 0) ? sbs[b - 1] : 0;

    int i0 = b * SCAN_CHUNK + t * SCAN_ITEMS;
    int v0 = (i0 + 0 < NB) ? g_cnt[i0 + 0] : 0;
    int v1 = (i0 + 1 < NB) ? g_cnt[i0 + 1] : 0;
    int v2 = (i0 + 2 < NB) ? g_cnt[i0 + 2] : 0;
    int v3 = (i0 + 3 < NB) ? g_cnt[i0 + 3] : 0;
    int tot = v0 + v1 + v2 + v3;
    sh[t] = tot;
    __syncthreads();
    for (int ofs = 1; ofs < SCAN_BLK; ofs <<= 1) {
        int add = (t >= ofs) ? sh[t - ofs] : 0;
        __syncthreads();
        sh[t] += add;
        __syncthreads();
    }
    int base = boff + sh[t] - tot;
    if (i0 + 0 < NB) g_off[i0 + 0] = base;  base += v0;
    if (i0 + 1 < NB) g_off[i0 + 1] = base;  base += v1;
    if (i0 + 2 < NB) g_off[i0 + 2] = base;  base += v2;
    if (i0 + 3 < NB) g_off[i0 + 3] = base;
    if (b == 0 && t == 0) g_off[NB] = EE;
}

// launch 3 (profiled slot): scatter {packed index, 1/n} into sorted order; re-zero g_cnt
__global__ void k_scatter(const int* __restrict__ src, const int* __restrict__ dst,
                          const int* __restrict__ et) {
    int e = blockIdx.x * blockDim.x + threadIdx.x;
    if (e >= EE) return;
    int r = et[e];
    int key = dst[e] * RR + r;
    int o = __ldg(&g_off[key]);
    int n = __ldg(&g_off[key + 1]) - o;      // adjacent load, same sector
    float wt = 1.0f / (float)n;              // n >= 1 (this edge exists)
    g_srt2[o + g_pos[e]] = make_int2((src[e] << 3) | r, __float_as_int(wt));
    if (e < NB) g_cnt[e] = 0;
}

// Dense pre-transform: 1 thread/node. T[i][r][:] = x_i @ W_r; self[i] = x_i @ root + b.
// All threads read identical smem addresses in lockstep -> broadcast, FMA-bound.
__global__ void __launch_bounds__(256) k_transform(const float* __restrict__ xin,
                                                   const float* __restrict__ W,
                                                   const float* __restrict__ root,
                                                   const float* __restrict__ bias,
                                                   float* __restrict__ T,
                                                   float* __restrict__ selfout) {
    __shared__ __align__(16) float sW[RR * 256];   // W[r][k][c]
    __shared__ __align__(16) float sR[256];
    __shared__ float sB[16];
    int t = threadIdx.x;
#pragma unroll
    for (int i = t; i < RR * 256; i += 256) sW[i] = __ldg(W + i);
    sR[t] = __ldg(root + t);
    if (t < 16) sB[t] = __ldg(bias + t);
    __syncthreads();

    int i = blockIdx.x * 256 + t;
    if (i >= NN) return;

    float x[16];
    const float4* xr = (const float4*)(xin + (size_t)i * 16);
#pragma unroll
    for (int j = 0; j < 4; j++) {
        float4 v = __ldg(xr + j);
        x[4 * j] = v.x; x[4 * j + 1] = v.y; x[4 * j + 2] = v.z; x[4 * j + 3] = v.w;
    }

    float4* Trow = (float4*)(T + (size_t)i * (RR * 16));
#pragma unroll 1
    for (int r = 0; r < RR; r++) {
        float acc[16];
#pragma unroll
        for (int c = 0; c < 16; c++) acc[c] = 0.0f;
        const float* Wr = sW + r * 256;
#pragma unroll
        for (int k = 0; k < 16; k++) {
            float xv = x[k];
#pragma unroll
            for (int c = 0; c < 16; c++) acc[c] = fmaf(xv, Wr[k * 16 + c], acc[c]);
        }
#pragma unroll
        for (int j = 0; j < 4; j++)
            Trow[r * 4 + j] = make_float4(acc[4 * j], acc[4 * j + 1], acc[4 * j + 2], acc[4 * j + 3]);
    }
    {
        float acc[16];
#pragma unroll
        for (int c = 0; c < 16; c++) acc[c] = sB[c];
#pragma unroll
        for (int k = 0; k < 16; k++) {
            float xv = x[k];
#pragma unroll
            for (int c = 0; c < 16; c++) acc[c] = fmaf(xv, sR[k * 16 + c], acc[c]);
        }
        float4* srow = (float4*)(selfout + (size_t)i * 16);
#pragma unroll
        for (int j = 0; j < 4; j++)
            srow[j] = make_float4(acc[4 * j], acc[4 * j + 1], acc[4 * j + 2], acc[4 * j + 3]);
    }
}

// Gather: 4 lanes/node walk the node's FULL contiguous edge range (uniform bounds, no
// per-relation state). acc_q += wt_e * T[packed_e][quarter q]. Unrolled x2 for MLP.
// L==1 relu -> g_h;  L==2 log-softmax -> out.
template <int L>
__global__ void __launch_bounds__(256) k_gather(const float* __restrict__ T,
                                                const float* __restrict__ selfin,
                                                float* __restrict__ out) {
    int t = threadIdx.x;
    int node = blockIdx.x * 64 + (t >> 2);
    if (node >= NN) return;          // warp = 8 nodes; warps retire whole
    int q = t & 3;
    const unsigned FULL = 0xFFFFFFFFu;

    int lo = __ldg(&g_off[node * RR]);
    int hi = __ldg(&g_off[node * RR + RR]);

    float4 acc = __ldg((const float4*)(selfin + (size_t)node * 16) + q);

    int i = lo;
    for (; i + 2 <= hi; i += 2) {
        int2 e0 = __ldg(&g_srt2[i]);
        int2 e1 = __ldg(&g_srt2[i + 1]);
        float4 t0 = __ldg((const float4*)(T + (size_t)e0.x * 16) + q);
        float4 t1 = __ldg((const float4*)(T + (size_t)e1.x * 16) + q);
        float w0 = __int_as_float(e0.y), w1 = __int_as_float(e1.y);
        acc.x = fmaf(w0, t0.x, acc.x); acc.y = fmaf(w0, t0.y, acc.y);
        acc.z = fmaf(w0, t0.z, acc.z); acc.w = fmaf(w0, t0.w, acc.w);
        acc.x = fmaf(w1, t1.x, acc.x); acc.y = fmaf(w1, t1.y, acc.y);
        acc.z = fmaf(w1, t1.z, acc.z); acc.w = fmaf(w1, t1.w, acc.w);
    }
    if (i < hi) {
        int2 e0 = __ldg(&g_srt2[i]);
        float4 t0 = __ldg((const float4*)(T + (size_t)e0.x * 16) + q);
        float w0 = __int_as_float(e0.y);
        acc.x = fmaf(w0, t0.x, acc.x); acc.y = fmaf(w0, t0.y, acc.y);
        acc.z = fmaf(w0, t0.z, acc.z); acc.w = fmaf(w0, t0.w, acc.w);
    }

    if (L == 1) {
        acc.x = fmaxf(acc.x, 0.0f); acc.y = fmaxf(acc.y, 0.0f);
        acc.z = fmaxf(acc.z, 0.0f); acc.w = fmaxf(acc.w, 0.0f);
    } else {
        // log-softmax across the 16 features spread over 4 lanes
        float m = fmaxf(fmaxf(acc.x, acc.y), fmaxf(acc.z, acc.w));
#pragma unroll
        for (int o = 1; o <= 2; o <<= 1) m = fmaxf(m, __shfl_xor_sync(FULL, m, o));
        float s = expf(acc.x - m) + expf(acc.y - m) + expf(acc.z - m) + expf(acc.w - m);
#pragma unroll
        for (int o = 1; o <= 2; o <<= 1) s += __shfl_xor_sync(FULL, s, o);
        float l = m + logf(s);
        acc.x -= l; acc.y -= l; acc.z -= l; acc.w -= l;
    }
    ((float4*)(out + (size_t)node * 16))[q] = acc;
}

extern "C" void kernel_launch(void* const* d_in, const int* in_sizes, int n_in,
                              void* d_out, int out_size) {
    const float* embed = (const float*)d_in[0];
    const float* W1    = (const float*)d_in[1];
    const float* root1 = (const float*)d_in[2];
    const float* b1    = (const float*)d_in[3];
    const float* W2    = (const float*)d_in[4];
    const float* root2 = (const float*)d_in[5];
    const float* b2    = (const float*)d_in[6];
    const int*   ei    = (const int*)d_in[7];   // [2, E]
    const int*   et    = (const int*)d_in[8];   // [E]
    const int* src = ei;
    const int* dst = ei + EE;
    float* out = (float*)d_out;
    (void)in_sizes; (void)n_in; (void)out_size;

    const int TB = 256;

    k_hist<<<(EE + TB - 1) / TB, TB>>>(dst, et);          // 0
    k_scan_reduce<<<SCAN_NBLK, SCAN_BLK>>>();             // 1
    k_scan_write<<<SCAN_NBLK, SCAN_BLK>>>();              // 2
    k_scatter<<<(EE + TB - 1) / TB, TB>>>(src, dst, et);  // 3  <- profiled slot

    int tr_blocks = (NN + 255) / 256;
    int ga_blocks = (NN + 63) / 64;
    // layer 1
    k_transform<<<tr_blocks, 256>>>(embed, W1, root1, b1, g_T, g_s);  // 4
    k_gather<1><<<ga_blocks, 256>>>(g_T, g_s, g_h);                   // 5
    // layer 2
    k_transform<<<tr_blocks, 256>>>(g_h, W2, root2, b2, g_T, g_s);    // 6
    k_gather<2><<<ga_blocks, 256>>>(g_T, g_s, out);                   // 7
}

// round 10
// speedup vs baseline: 4.1497x; 4.1497x over previous
#include <cuda_runtime.h>

#define NN 100000
#define EE 3200000
#define RR 8
#define NB (NN * RR)

// ---- device scratch (zero-initialized at module load) ----
__device__ __align__(16) int   g_cnt[NB];        // per-(dst,rel) edge counts; zeroed in k_matvec<2>
__device__ __align__(16) float g_S[NB * 16];     // per-(dst,rel) raw feature sums; zeroed in k_matvec epilogue
__device__ __align__(16) float g_h[NN * 16];     // layer-1 output

// launch 0: per-(dst,rel) edge counts (one int atomic per edge, 800K spread addresses)
__global__ void k_hist(const int* __restrict__ dst, const int* __restrict__ et) {
    int e = blockIdx.x * blockDim.x + threadIdx.x;
    if (e >= EE) return;
    atomicAdd(&g_cnt[dst[e] * RR + et[e]], 1);
}

// edge pass: red x[src] row into S[dst*8+rel]. 12.8M v4-reds over 3.2M float4 addresses
// (avg 4 ops/address -> spread-REDG regime). All loads independent -> latency fully hidden.
__global__ void __launch_bounds__(256) k_edge(const float* __restrict__ xin,
                                              const int* __restrict__ src,
                                              const int* __restrict__ dst,
                                              const int* __restrict__ et) {
    int e = blockIdx.x * blockDim.x + threadIdx.x;
    if (e >= EE) return;
    int s = __ldg(src + e);
    int key = __ldg(dst + e) * RR + __ldg(et + e);
    const float4* px = (const float4*)(xin + (size_t)s * 16);
    float* Sp = g_S + (size_t)key * 16;
    float4 v0 = __ldg(px + 0), v1 = __ldg(px + 1), v2 = __ldg(px + 2), v3 = __ldg(px + 3);
    asm volatile("red.global.add.v4.f32 [%0], {%1,%2,%3,%4};" ::
                 "l"(Sp + 0), "f"(v0.x), "f"(v0.y), "f"(v0.z), "f"(v0.w) : "memory");
    asm volatile("red.global.add.v4.f32 [%0], {%1,%2,%3,%4};" ::
                 "l"(Sp + 4), "f"(v1.x), "f"(v1.y), "f"(v1.z), "f"(v1.w) : "memory");
    asm volatile("red.global.add.v4.f32 [%0], {%1,%2,%3,%4};" ::
                 "l"(Sp + 8), "f"(v2.x), "f"(v2.y), "f"(v2.z), "f"(v2.w) : "memory");
    asm volatile("red.global.add.v4.f32 [%0], {%1,%2,%3,%4};" ::
                 "l"(Sp + 12), "f"(v3.x), "f"(v3.y), "f"(v3.z), "f"(v3.w) : "memory");
}

// node pass: out_i = sum_r (S[i,r]/n_{i,r}) @ W_r + x_i @ root + b, then epilogue.
// S rows read sequentially (512B/node) and zeroed after use (replay-safe).
// All weight smem reads are warp-uniform -> broadcast, conflict-free.
// L==1: relu -> g_h.  L==2: log-softmax -> out; also zeroes g_cnt.
template <int L>
__global__ void __launch_bounds__(256) k_matvec(const float* __restrict__ xin,
                                                const float* __restrict__ W,
                                                const float* __restrict__ root,
                                                const float* __restrict__ bias,
                                                float* __restrict__ out) {
    __shared__ __align__(16) float sW[RR * 256];   // W[r][k][c]
    __shared__ __align__(16) float sR[256];        // root[k][c]
    __shared__ float sB[16];
    int t = threadIdx.x;
#pragma unroll
    for (int i = t; i < RR * 256; i += 256) sW[i] = __ldg(W + i);
    sR[t] = __ldg(root + t);
    if (t < 16) sB[t] = __ldg(bias + t);
    __syncthreads();

    int node = blockIdx.x * 256 + t;
    if (node >= NN) return;

    // per-relation 1/n (0 if empty -> S row is zero anyway, avoids inf*0)
    float inv[RR];
    {
        const int4* cp = (const int4*)(g_cnt + node * RR);
        int4 c0 = __ldg(cp + 0), c1 = __ldg(cp + 1);
        int cn[RR] = {c0.x, c0.y, c0.z, c0.w, c1.x, c1.y, c1.z, c1.w};
#pragma unroll
        for (int r = 0; r < RR; r++) inv[r] = (cn[r] > 0) ? 1.0f / (float)cn[r] : 0.0f;
    }

    float acc[16];
#pragma unroll
    for (int c = 0; c < 16; c++) acc[c] = sB[c];

    // self term
    {
        const float4* xr = (const float4*)(xin + (size_t)node * 16);
#pragma unroll
        for (int j = 0; j < 4; j++) {
            float4 v = __ldg(xr + j);
            float xs[4] = {v.x, v.y, v.z, v.w};
#pragma unroll
            for (int kk = 0; kk < 4; kk++) {
                float xv = xs[kk];
                const float* Rk = sR + (4 * j + kk) * 16;
#pragma unroll
                for (int c = 0; c < 16; c++) acc[c] = fmaf(xv, Rk[c], acc[c]);
            }
        }
    }

    // relation terms: (S_r * inv_r) @ W_r  (S read sequential, then zeroed)
    float4* Srow = (float4*)(g_S + (size_t)node * (RR * 16));
#pragma unroll 1
    for (int r = 0; r < RR; r++) {
        float iv = inv[r];
        const float* Wr = sW + r * 256;
#pragma unroll
        for (int j = 0; j < 4; j++) {
            float4 v = Srow[r * 4 + j];
            float vs[4] = {v.x * iv, v.y * iv, v.z * iv, v.w * iv};
#pragma unroll
            for (int kk = 0; kk < 4; kk++) {
                float xv = vs[kk];
                const float* Wk = Wr + (4 * j + kk) * 16;
#pragma unroll
                for (int c = 0; c < 16; c++) acc[c] = fmaf(xv, Wk[c], acc[c]);
            }
        }
    }
    // zero S for the next use/replay
    {
        float4 z = make_float4(0.f, 0.f, 0.f, 0.f);
#pragma unroll
        for (int j = 0; j < RR * 4; j++) Srow[j] = z;
    }
    if (L == 2) {  // zero counts for next replay (after both layers used them)
        int4 zi = make_int4(0, 0, 0, 0);
        int4* cp = (int4*)(g_cnt + node * RR);
        cp[0] = zi; cp[1] = zi;
    }

    if (L == 1) {
#pragma unroll
        for (int c = 0; c < 16; c++) acc[c] = fmaxf(acc[c], 0.0f);
    } else {
        float m = acc[0];
#pragma unroll
        for (int c = 1; c < 16; c++) m = fmaxf(m, acc[c]);
        float s = 0.0f;
#pragma unroll
        for (int c = 0; c < 16; c++) s += expf(acc[c] - m);
        float l = m + logf(s);
#pragma unroll
        for (int c = 0; c < 16; c++) acc[c] -= l;
    }

    float4* orow = (float4*)(out + (size_t)node * 16);
#pragma unroll
    for (int j = 0; j < 4; j++)
        orow[j] = make_float4(acc[4 * j], acc[4 * j + 1], acc[4 * j + 2], acc[4 * j + 3]);
}

extern "C" void kernel_launch(void* const* d_in, const int* in_sizes, int n_in,
                              void* d_out, int out_size) {
    const float* embed = (const float*)d_in[0];
    const float* W1    = (const float*)d_in[1];
    const float* root1 = (const float*)d_in[2];
    const float* b1    = (const float*)d_in[3];
    const float* W2    = (const float*)d_in[4];
    const float* root2 = (const float*)d_in[5];
    const float* b2    = (const float*)d_in[6];
    const int*   ei    = (const int*)d_in[7];   // [2, E]
    const int*   et    = (const int*)d_in[8];   // [E]
    const int* src = ei;
    const int* dst = ei + EE;
    float* out = (float*)d_out;
    (void)in_sizes; (void)n_in; (void)out_size;

    const int TB = 256;
    int eb = (EE + TB - 1) / TB;
    int nb = (NN + TB - 1) / TB;

    k_hist<<<eb, TB>>>(dst, et);                            // 0
    k_edge<<<eb, TB>>>(embed, src, dst, et);                // 1
    k_matvec<1><<<nb, TB>>>(embed, W1, root1, b1, g_h);     // 2
    k_edge<<<eb, TB>>>(g_h, src, dst, et);                  // 3  <- profiled slot
    k_matvec<2><<<nb, TB>>>(g_h, W2, root2, b2, out);       // 4
}